// round 14
// baseline (speedup 1.0000x reference)
#include <cuda_runtime.h>
#include <math.h>

#define Nn     8192
#define Bb     4
#define Ee     262144
#define HIDDEN 512
#define OUTD   64
#define DCAP   127
#define TROWS  (DCAP + 1)          // 128 table rows
#define NB     288                 // 2/SM * 152 SMs = 304 capacity >= 288 (proven r11)
#define NT     512
// role map
#define VB0    0
#define VBN    64                  // vec blocks 0..63 -> fixup afterwards
#define CLB    64                  // cleanup block -> node afterwards
#define HB0    65
#define HBN    64                  // hist blocks 65..128 (16 slices per graph) -> node
#define TB0    129
#define TBN    16                  // table blocks 129..144 (8 rows each) -> node
#define NP0    64                  // node pool = bids 64..287 (224 blocks)
#define NPN    224

// Scratch (allocation-free rule: __device__ globals; zero-initialized at load)
__device__ int   g_outdeg[Bb * Nn];
__device__ __align__(16) int g_cnt[Bb * Nn * 4];
__device__ int   g_mark[Bb * Nn];
__device__ float g_vec[5 * HIDDEN];
__device__ float g_table[TROWS * OUTD];
__device__ int   g_queue[Bb * Nn];
__device__ int   g_qcnt;
__device__ unsigned g_vec_done, g_clean_done, g_hist_done, g_table_done, g_exit_cnt;

// Shared union: hist histogram (32KB) OR pipeline workspace (17KB)
struct PipeWS {
    float sh[8][HIDDEN];           // 16 KB
    float rs[8][16], rq[8][16];
    float smu[8], sinv[8];
};

__device__ __forceinline__ void spin_ge(unsigned* flag, unsigned val) {
    if (threadIdx.x == 0) {
        while (atomicAdd(flag, 0u) < val) { }
        __threadfence();
    }
    __syncthreads();
}
__device__ __forceinline__ void signal(unsigned* flag) {
    __syncthreads();
    if (threadIdx.x == 0) { __threadfence(); atomicAdd(flag, 1u); }
}

// ---------------------------------------------------------------------------
// Batched 512-thread pipeline: 8 nodes. float4 GEMV (conflict-free LDS.128).
__device__ __forceinline__ void pipeline8(
    PipeWS* ws,
    const float* __restrict__ sdg, const float (*__restrict__ scc)[4],
    float* const* __restrict__ souts,
    const float* __restrict__ b1, const float* __restrict__ ln_g,
    const float* __restrict__ ln_b, const float* __restrict__ w2,
    const float* __restrict__ b2) {
    int t = threadIdx.x;

    float v0 = g_vec[t];
    float v1 = g_vec[HIDDEN + t],     v2 = g_vec[2 * HIDDEN + t];
    float v3 = g_vec[3 * HIDDEN + t], v4 = g_vec[4 * HIDDEN + t];
    float b1t = b1[t];

    float ps[8], pq[8];
    #pragma unroll
    for (int i = 0; i < 8; i++) {
        float h = b1t + sdg[i] * v0 + scc[i][0] * v1 + scc[i][1] * v2
                                    + scc[i][2] * v3 + scc[i][3] * v4;
        ws->sh[i][t] = h;
        ps[i] = h; pq[i] = h * h;
    }
    #pragma unroll
    for (int o = 16; o > 0; o >>= 1) {
        #pragma unroll
        for (int i = 0; i < 8; i++) {
            ps[i] += __shfl_down_sync(0xffffffffu, ps[i], o);
            pq[i] += __shfl_down_sync(0xffffffffu, pq[i], o);
        }
    }
    if ((t & 31) == 0) {
        #pragma unroll
        for (int i = 0; i < 8; i++) { ws->rs[i][t >> 5] = ps[i]; ws->rq[i][t >> 5] = pq[i]; }
    }
    __syncthreads();
    if (t < 32) {
        #pragma unroll
        for (int i = 0; i < 8; i++) {
            float a = (t < 16) ? ws->rs[i][t] : 0.f;
            float q = (t < 16) ? ws->rq[i][t] : 0.f;
            #pragma unroll
            for (int o = 8; o > 0; o >>= 1) {
                a += __shfl_down_sync(0xffffffffu, a, o);
                q += __shfl_down_sync(0xffffffffu, q, o);
            }
            if (t == 0) {
                float mu  = a * (1.f / HIDDEN);
                float var = q * (1.f / HIDDEN) - mu * mu;
                ws->smu[i]  = mu;
                ws->sinv[i] = rsqrtf(var + 1e-5f);
            }
        }
    }
    __syncthreads();

    float g = ln_g[t], bb = ln_b[t];
    #pragma unroll
    for (int i = 0; i < 8; i++) {
        float x = (ws->sh[i][t] - ws->smu[i]) * ws->sinv[i] * g + bb;
        ws->sh[i][t] = 0.5f * x * (1.f + erff(x * 0.7071067811865476f));  // exact GELU
    }
    __syncthreads();

    // GEMV: thread (o=t>>3, part=t&7); float4 on sh and w2.
    int o = t >> 3, part = t & 7;
    const float4* w2r4 = (const float4*)(w2 + (size_t)o * HIDDEN) + part;
    float acc[8] = {0.f, 0.f, 0.f, 0.f, 0.f, 0.f, 0.f, 0.f};
    #pragma unroll
    for (int j = 0; j < HIDDEN / 32; j++) {          // 16 iters
        float4 w = w2r4[8 * j];
        #pragma unroll
        for (int i = 0; i < 8; i++) {
            float4 hv = ((const float4*)ws->sh[i])[part + 8 * j];
            acc[i] += hv.x * w.x + hv.y * w.y + hv.z * w.z + hv.w * w.w;
        }
    }
    #pragma unroll
    for (int off = 4; off > 0; off >>= 1) {
        #pragma unroll
        for (int i = 0; i < 8; i++)
            acc[i] += __shfl_down_sync(0xffffffffu, acc[i], off);
    }
    if (part == 0) {
        float bo = b2[o];
        #pragma unroll
        for (int i = 0; i < 8; i++) souts[i][o] = acc[i] + bo;
    }
    __syncthreads();
}

// ===========================================================================
__global__ void __launch_bounds__(NT, 2)
mono_kernel(const int* __restrict__ ei, const int* __restrict__ pert,
            const float* __restrict__ proj_w, const float* __restrict__ proj_b,
            const float* __restrict__ w1, const float* __restrict__ b1,
            const float* __restrict__ ln_g, const float* __restrict__ ln_b,
            const float* __restrict__ w2, const float* __restrict__ b2,
            float* __restrict__ out) {
    __shared__ __align__(16) unsigned char sbuf[sizeof(int) * Nn];  // 32KB union
    PipeWS* ws = (PipeWS*)sbuf;
    int* hc = (int*)sbuf;
    __shared__ float sdg[8];
    __shared__ float scc[8][4];
    __shared__ float* souts[8];
    int bid = blockIdx.x, t = threadIdx.x;

    // ---------------- Role phase ------------------------------------------
    if (bid < VBN) {
        // vec: 8 k's per block, 64 threads per k.  omega[n,j]=H[n,j/4] =>
        // w1s[k,e] = sum_{m<4} w1[k, e*4+m]; v0=w1s.proj_b; vb=w1s.proj_w[:,b]
        __shared__ float pr[16][5];
        int e = t & 63;
        int k = bid * 8 + (t >> 6);
        float4 w4 = __ldg((const float4*)(w1 + (size_t)k * 256 + e * 4));
        float s = w4.x + w4.y + w4.z + w4.w;
        float4 pw = __ldg((const float4*)(proj_w + e * 4));
        float a0 = s * __ldg(proj_b + e);
        float a1 = s * pw.x, a2 = s * pw.y, a3 = s * pw.z, a4 = s * pw.w;
        #pragma unroll
        for (int o = 16; o > 0; o >>= 1) {
            a0 += __shfl_down_sync(0xffffffffu, a0, o);
            a1 += __shfl_down_sync(0xffffffffu, a1, o);
            a2 += __shfl_down_sync(0xffffffffu, a2, o);
            a3 += __shfl_down_sync(0xffffffffu, a3, o);
            a4 += __shfl_down_sync(0xffffffffu, a4, o);
        }
        if ((t & 31) == 0) {
            int w = t >> 5;
            pr[w][0] = a0; pr[w][1] = a1; pr[w][2] = a2; pr[w][3] = a3; pr[w][4] = a4;
        }
        __syncthreads();
        if (t < 8) {
            int kk = bid * 8 + t;
            g_vec[kk]              = pr[t * 2][0] + pr[t * 2 + 1][0];
            g_vec[HIDDEN + kk]     = pr[t * 2][1] + pr[t * 2 + 1][1];
            g_vec[2 * HIDDEN + kk] = pr[t * 2][2] + pr[t * 2 + 1][2];
            g_vec[3 * HIDDEN + kk] = pr[t * 2][3] + pr[t * 2 + 1][3];
            g_vec[4 * HIDDEN + kk] = pr[t * 2][4] + pr[t * 2 + 1][4];
        }
        signal(&g_vec_done);
        // ---- then: fixup (needs all vec + all hist) ----
        spin_ge(&g_vec_done, VBN);
        spin_ge(&g_hist_done, HBN);
        int qn = g_qcnt;
        for (int q0 = bid * 8; q0 < qn; q0 += VBN * 8) {
            if (t < 8) {
                int q = q0 + t; if (q >= qn) q = qn - 1;   // tail duplicate, benign
                int bn = g_queue[q];
                sdg[t] = (float)g_outdeg[bn];
                int4 c = *(const int4*)(g_cnt + (size_t)bn * 4);
                scc[t][0] = (float)c.x; scc[t][1] = (float)c.y;
                scc[t][2] = (float)c.z; scc[t][3] = (float)c.w;
                souts[t] = out + (size_t)bn * OUTD;
            }
            __syncthreads();
            pipeline8(ws, sdg, scc, souts, b1, ln_g, ln_b, w2, b2);
        }
    } else if (bid == CLB) {
        // cleanup: reset state dirtied by PREVIOUS call's marked nodes
        int qn = g_qcnt;
        for (int q = t; q < qn; q += NT) {
            int bn = g_queue[q];
            g_outdeg[bn] = 0;
            g_mark[bn]   = 0;
            *(int4*)(g_cnt + (size_t)bn * 4) = make_int4(0, 0, 0, 0);
        }
        __syncthreads();
        if (t == 0) { g_qcnt = 0; __threadfence(); atomicAdd(&g_clean_done, 1u); }
    } else if (bid < TB0) {
        // hist: smem-privatized; 16 slices per graph
        __shared__ int p[4];
        if (t < 4) p[t] = pert[t];
        for (int i = t; i < Nn; i += NT) hc[i] = 0;
        spin_ge(&g_clean_done, 1u);
        int hb  = bid - HB0;                         // 0..63
        int gph = hb >> 4;                           // graph
        int sl  = hb & 15;                           // slice
        const int QS = (Ee / 4) / 16;                // 4096 quads per slice
        const int* base = ei + (size_t)gph * 2 * Ee;
        int gb = gph * Nn;
        for (int q = sl * QS + t; q < (sl + 1) * QS; q += NT) {   // 8 iters
            int4 src = __ldg((const int4*)(base + q * 4));
            int4 dst = __ldg((const int4*)(base + Ee + q * 4));
            #pragma unroll
            for (int j = 0; j < 4; j++) {
                int s = (j == 0) ? src.x : (j == 1) ? src.y : (j == 2) ? src.z : src.w;
                int d = (j == 0) ? dst.x : (j == 1) ? dst.y : (j == 2) ? dst.z : dst.w;
                atomicAdd(&hc[s], 1);
                bool h0 = (d == p[0]), h1 = (d == p[1]), h2 = (d == p[2]), h3 = (d == p[3]);
                if (h0 | h1 | h2 | h3) {
                    int bn = gb + s;
                    int cb = bn * 4;
                    if (h0) atomicAdd(&g_cnt[cb + 0], 1);
                    if (h1) atomicAdd(&g_cnt[cb + 1], 1);
                    if (h2) atomicAdd(&g_cnt[cb + 2], 1);
                    if (h3) atomicAdd(&g_cnt[cb + 3], 1);
                    if (atomicOr(&g_mark[bn], 1) == 0) {
                        int qq = atomicAdd(&g_qcnt, 1);
                        g_queue[qq] = bn;
                    }
                }
            }
        }
        __syncthreads();
        for (int i = t; i < Nn; i += NT) {           // flush nonzero counters
            int c = hc[i];
            if (c) atomicAdd(&g_outdeg[gb + i], c);
        }
        signal(&g_hist_done);
    } else if (bid < TB0 + TBN) {
        // table: 8 rows per block, needs all vec
        if (t < 8) {
            int r = (bid - TB0) * 8 + t;             // 0..127
            sdg[t] = (float)r;
            scc[t][0] = scc[t][1] = scc[t][2] = scc[t][3] = 0.f;
            souts[t] = g_table + (size_t)r * OUTD;
        }
        spin_ge(&g_vec_done, VBN);
        pipeline8(ws, sdg, scc, souts, b1, ln_g, ln_b, w2, b2);
        signal(&g_table_done);
    }

    // ---------------- Node fast path (pool = bids >= NP0) ------------------
    if (bid >= NP0) {
        spin_ge(&g_table_done, TBN);
        spin_ge(&g_hist_done, HBN);
        int wid = t >> 5, lane = t & 31;
        for (int task = (bid - NP0) * 16 + wid; task < Bb * Nn / 8; task += NPN * 16) {
            int bn0 = task * 8;
            int mk = 0, dgl = 0;
            if (lane < 8) { mk = g_mark[bn0 + lane]; dgl = g_outdeg[bn0 + lane]; }
            float2 v[8];
            int deg[8], mark[8];
            #pragma unroll
            for (int i = 0; i < 8; i++) {
                mark[i] = __shfl_sync(0xffffffffu, mk,  i);
                deg[i]  = __shfl_sync(0xffffffffu, dgl, i);
                int d = (deg[i] <= DCAP) ? deg[i] : DCAP;
                v[i] = __ldg((const float2*)(g_table + d * OUTD + lane * 2));  // MLP=8
            }
            if (lane < 8 && !mk) g_outdeg[bn0 + lane] = 0;   // self-clean unmarked
            #pragma unroll
            for (int i = 0; i < 8; i++) {
                if (mark[i]) continue;                       // fixup owns it
                if (deg[i] <= DCAP) {
                    float2* dst = (float2*)(out + (size_t)(bn0 + i) * OUTD + lane * 2);
                    __stcs(dst, v[i]);
                    continue;
                }
                // never-taken safety path (Poisson(32)): in-warp full pipeline
                float dgf = (float)deg[i];
                float hreg[16];
                float ps = 0.f, pq = 0.f;
                #pragma unroll
                for (int r = 0; r < 16; r++) {
                    int k = lane + 32 * r;
                    float h = b1[k] + dgf * g_vec[k];
                    hreg[r] = h; ps += h; pq += h * h;
                }
                #pragma unroll
                for (int o = 16; o > 0; o >>= 1) {
                    ps += __shfl_xor_sync(0xffffffffu, ps, o);
                    pq += __shfl_xor_sync(0xffffffffu, pq, o);
                }
                float mu  = ps * (1.f / HIDDEN);
                float var = pq * (1.f / HIDDEN) - mu * mu;
                float inv = rsqrtf(var + 1e-5f);
                #pragma unroll
                for (int r = 0; r < 16; r++) {
                    int k = lane + 32 * r;
                    float x = (hreg[r] - mu) * inv * ln_g[k] + ln_b[k];
                    hreg[r] = 0.5f * x * (1.f + erff(x * 0.7071067811865476f));
                }
                for (int o = 0; o < OUTD; o++) {
                    float acc = 0.f;
                    const float* w2r = w2 + (size_t)o * HIDDEN + lane;
                    #pragma unroll
                    for (int r = 0; r < 16; r++) acc += hreg[r] * w2r[32 * r];
                    #pragma unroll
                    for (int off = 16; off > 0; off >>= 1)
                        acc += __shfl_xor_sync(0xffffffffu, acc, off);
                    if (lane == 0) out[(size_t)(bn0 + i) * OUTD + o] = acc + b2[o];
                }
            }
        }
    }

    // ---------------- Exit: last block resets all flags --------------------
    __syncthreads();
    if (t == 0) {
        __threadfence();
        unsigned n = atomicAdd(&g_exit_cnt, 1u);
        if (n == (unsigned)NB - 1u) {
            g_vec_done = 0u; g_clean_done = 0u; g_hist_done = 0u;
            g_table_done = 0u; g_exit_cnt = 0u;
            __threadfence();
        }
    }
}

// ===========================================================================
extern "C" void kernel_launch(void* const* d_in, const int* in_sizes, int n_in,
                              void* d_out, int out_size) {
    const int*   ei     = (const int*)  d_in[0];
    const int*   pert   = (const int*)  d_in[1];
    const float* proj_w = (const float*)d_in[2];
    const float* proj_b = (const float*)d_in[3];
    const float* w1     = (const float*)d_in[4];
    const float* b1     = (const float*)d_in[5];
    const float* ln_g   = (const float*)d_in[6];
    const float* ln_b   = (const float*)d_in[7];
    const float* w2     = (const float*)d_in[8];
    const float* b2     = (const float*)d_in[9];
    float* out = (float*)d_out;

    mono_kernel<<<NB, NT>>>(ei, pert, proj_w, proj_b, w1, b1, ln_g, ln_b, w2, b2, out);
}

// round 15
// speedup vs baseline: 1.7827x; 1.7827x over previous
#include <cuda_runtime.h>
#include <math.h>

#define Nn     8192
#define Bb     4
#define Ee     262144
#define HIDDEN 512
#define OUTD   64
#define DCAP   192
#define TROWS  (DCAP + 1)          // 193 table rows
#define VBLK   64                  // vec blocks (8 k's each)
#define CLB    64                  // cleanup block id
#define TB0    65                  // table blocks [TB0, TB0+25)
#define TBLK8  25
#define HB0    (TB0 + TBLK8)       // hist blocks [HB0, HB0+32)
#define HB     32                  // 8 per graph, smem-privatized
#define SLG    8                   // slices per graph
#define KA_NB  (HB0 + HB)          // 122 blocks, all wave-1 resident
#define FBLK8  80                  // fixup blocks (8 nodes each)
#define NODEB  256                 // node fast-path blocks

// Scratch (allocation-free rule: __device__ globals; zero-initialized at load)
__device__ int   g_outdeg[Bb * Nn];
__device__ __align__(16) int g_cnt[Bb * Nn * 4];
__device__ int   g_mark[Bb * Nn];
__device__ float g_vec[5 * HIDDEN];
__device__ float g_table[TROWS * OUTD];
__device__ int   g_queue[Bb * Nn];
__device__ int   g_qcnt;
__device__ unsigned g_vecdone;     // reset by K_B block 0
__device__ unsigned g_cleandone;   // reset by K_B block 0

// ===========================================================================
// Batched 512-thread pipeline: 8 nodes per block. float4 GEMV
// (conflict-free LDS.128: 8 parts * 16B = one contiguous 128B line).
// h = b1 + deg*v0 + sum cnt_b*v_b ; LN ; exact GELU ; @ w2.T + b2
__device__ __forceinline__ void pipeline8(
    const float* __restrict__ sdg, const float (*__restrict__ scc)[4],
    float* const* __restrict__ souts,
    const float* __restrict__ b1, const float* __restrict__ ln_g,
    const float* __restrict__ ln_b, const float* __restrict__ w2,
    const float* __restrict__ b2) {

    __shared__ __align__(16) float sh[8][HIDDEN];    // 16 KB
    __shared__ float rs[8][16], rq[8][16];
    __shared__ float smu[8], sinv[8];
    int t = threadIdx.x;

    float v0 = g_vec[t];
    float v1 = g_vec[HIDDEN + t],     v2 = g_vec[2 * HIDDEN + t];
    float v3 = g_vec[3 * HIDDEN + t], v4 = g_vec[4 * HIDDEN + t];
    float b1t = b1[t];

    float ps[8], pq[8];
    #pragma unroll
    for (int i = 0; i < 8; i++) {
        float h = b1t + sdg[i] * v0 + scc[i][0] * v1 + scc[i][1] * v2
                                    + scc[i][2] * v3 + scc[i][3] * v4;
        sh[i][t] = h;
        ps[i] = h; pq[i] = h * h;
    }
    #pragma unroll
    for (int o = 16; o > 0; o >>= 1) {
        #pragma unroll
        for (int i = 0; i < 8; i++) {
            ps[i] += __shfl_down_sync(0xffffffffu, ps[i], o);
            pq[i] += __shfl_down_sync(0xffffffffu, pq[i], o);
        }
    }
    if ((t & 31) == 0) {
        #pragma unroll
        for (int i = 0; i < 8; i++) { rs[i][t >> 5] = ps[i]; rq[i][t >> 5] = pq[i]; }
    }
    __syncthreads();
    if (t < 32) {
        #pragma unroll
        for (int i = 0; i < 8; i++) {
            float a = (t < 16) ? rs[i][t] : 0.f;
            float q = (t < 16) ? rq[i][t] : 0.f;
            #pragma unroll
            for (int o = 8; o > 0; o >>= 1) {
                a += __shfl_down_sync(0xffffffffu, a, o);
                q += __shfl_down_sync(0xffffffffu, q, o);
            }
            if (t == 0) {
                float mu  = a * (1.f / HIDDEN);
                float var = q * (1.f / HIDDEN) - mu * mu;
                smu[i]  = mu;
                sinv[i] = rsqrtf(var + 1e-5f);
            }
        }
    }
    __syncthreads();

    float g = ln_g[t], bb = ln_b[t];
    #pragma unroll
    for (int i = 0; i < 8; i++) {
        float x = (sh[i][t] - smu[i]) * sinv[i] * g + bb;
        sh[i][t] = 0.5f * x * (1.f + erff(x * 0.7071067811865476f));  // exact GELU
    }
    __syncthreads();

    // GEMV: thread (o=t>>3, part=t&7); float4 loads on sh and w2.
    int o = t >> 3, part = t & 7;
    const float4* w2r4 = (const float4*)(w2 + (size_t)o * HIDDEN) + part;
    float acc[8] = {0.f, 0.f, 0.f, 0.f, 0.f, 0.f, 0.f, 0.f};
    #pragma unroll
    for (int j = 0; j < HIDDEN / 32; j++) {          // 16 iters
        float4 w = w2r4[8 * j];
        #pragma unroll
        for (int i = 0; i < 8; i++) {
            float4 hv = ((const float4*)sh[i])[part + 8 * j];
            acc[i] += hv.x * w.x + hv.y * w.y + hv.z * w.z + hv.w * w.w;
        }
    }
    #pragma unroll
    for (int off = 4; off > 0; off >>= 1) {
        #pragma unroll
        for (int i = 0; i < 8; i++)
            acc[i] += __shfl_down_sync(0xffffffffu, acc[i], off);
    }
    if (part == 0) {
        float bo = b2[o];
        #pragma unroll
        for (int i = 0; i < 8; i++) souts[i][o] = acc[i] + bo;
    }
    __syncthreads();
}

// ===========================================================================
// K_A: vec + cleanup + table + hist in one launch, ordered by device flags.
// 122 blocks <= SM count => all resident => spin-waits are deadlock-free.
__global__ void __launch_bounds__(512, 2)
ka_kernel(const int* __restrict__ ei, const int* __restrict__ pert,
          const float* __restrict__ proj_w, const float* __restrict__ proj_b,
          const float* __restrict__ w1, const float* __restrict__ b1,
          const float* __restrict__ ln_g, const float* __restrict__ ln_b,
          const float* __restrict__ w2, const float* __restrict__ b2) {
    int bid = blockIdx.x, t = threadIdx.x;

    if (bid < VBLK) {
        // ---- vec: 8 k's per block, 64 threads per k, one e each ----
        // omega[n,j] = H[n, j/4]  =>  w1s[k,e] = sum_{m<4} w1[k, e*4+m]
        int e = t & 63;
        int k = bid * 8 + (t >> 6);
        float4 w4 = __ldg((const float4*)(w1 + (size_t)k * 256 + e * 4));
        float s = w4.x + w4.y + w4.z + w4.w;
        float4 pw = __ldg((const float4*)(proj_w + e * 4));   // (EMBED,B) row-major
        float a0 = s * __ldg(proj_b + e);
        float a1 = s * pw.x, a2 = s * pw.y, a3 = s * pw.z, a4 = s * pw.w;
        #pragma unroll
        for (int o = 16; o > 0; o >>= 1) {
            a0 += __shfl_down_sync(0xffffffffu, a0, o);
            a1 += __shfl_down_sync(0xffffffffu, a1, o);
            a2 += __shfl_down_sync(0xffffffffu, a2, o);
            a3 += __shfl_down_sync(0xffffffffu, a3, o);
            a4 += __shfl_down_sync(0xffffffffu, a4, o);
        }
        __shared__ float pr[16][5];
        if ((t & 31) == 0) {
            int w = t >> 5;
            pr[w][0] = a0; pr[w][1] = a1; pr[w][2] = a2; pr[w][3] = a3; pr[w][4] = a4;
        }
        __syncthreads();
        if (t < 8) {
            int kk = bid * 8 + t;
            g_vec[kk]              = pr[t * 2][0] + pr[t * 2 + 1][0];
            g_vec[HIDDEN + kk]     = pr[t * 2][1] + pr[t * 2 + 1][1];
            g_vec[2 * HIDDEN + kk] = pr[t * 2][2] + pr[t * 2 + 1][2];
            g_vec[3 * HIDDEN + kk] = pr[t * 2][3] + pr[t * 2 + 1][3];
            g_vec[4 * HIDDEN + kk] = pr[t * 2][4] + pr[t * 2 + 1][4];
        }
        __syncthreads();
        if (t == 0) { __threadfence(); atomicAdd(&g_vecdone, 1u); }
        return;
    }
    if (bid == CLB) {
        // ---- cleanup: reset state dirtied by PREVIOUS call's marked nodes ----
        int qn = g_qcnt;
        for (int q = t; q < qn; q += 512) {
            int bn = g_queue[q];
            g_outdeg[bn] = 0;
            g_mark[bn]   = 0;
            *(int4*)(g_cnt + (size_t)bn * 4) = make_int4(0, 0, 0, 0);
        }
        __syncthreads();
        if (t == 0) {
            g_qcnt = 0;
            __threadfence();
            atomicExch(&g_cleandone, 1u);
        }
        return;
    }
    if (bid < HB0) {
        // ---- table: wait for vec, then 8 rows per block ----
        __shared__ float sdg[8];
        __shared__ float scc[8][4];
        __shared__ float* souts[8];
        if (t < 8) {
            int r = (bid - TB0) * 8 + t;
            if (r > DCAP) r = DCAP;                  // duplicate write, benign
            sdg[t] = (float)r;
            scc[t][0] = scc[t][1] = scc[t][2] = scc[t][3] = 0.f;
            souts[t] = g_table + (size_t)r * OUTD;
        }
        if (t == 0) {
            while (atomicAdd(&g_vecdone, 0u) < (unsigned)VBLK) { }
            __threadfence();
        }
        __syncthreads();
        pipeline8(sdg, scc, souts, b1, ln_g, ln_b, w2, b2);
        return;
    }
    // ---- hist: smem-privatized; global atomics gated on cleanup ----
    __shared__ int hc[Nn];                           // 32 KB
    __shared__ int p[4];
    if (t < 4) p[t] = pert[t];
    for (int i = t; i < Nn; i += 512) hc[i] = 0;
    if (t == 0) {
        while (atomicAdd(&g_cleandone, 0u) == 0u) { }
        __threadfence();
    }
    __syncthreads();

    int hb  = bid - HB0;                             // 0..HB-1
    int gph = hb / SLG;                              // graph 0..3
    int sl  = hb % SLG;                              // slice 0..7
    const int QS = (Ee / 4) / SLG;                   // 8192 quads per slice
    const int* base = ei + (size_t)gph * 2 * Ee;
    int gb = gph * Nn;

    #pragma unroll 2
    for (int q = sl * QS + t; q < (sl + 1) * QS; q += 512) {   // 16 iters
        int4 src = __ldg((const int4*)(base + q * 4));
        int4 dst = __ldg((const int4*)(base + Ee + q * 4));
        #pragma unroll
        for (int j = 0; j < 4; j++) {
            int s = (j == 0) ? src.x : (j == 1) ? src.y : (j == 2) ? src.z : src.w;
            int d = (j == 0) ? dst.x : (j == 1) ? dst.y : (j == 2) ? dst.z : dst.w;
            atomicAdd(&hc[s], 1);                    // smem atomic, cheap
            bool h0 = (d == p[0]), h1 = (d == p[1]), h2 = (d == p[2]), h3 = (d == p[3]);
            if (h0 | h1 | h2 | h3) {
                int bn = gb + s;
                int cb = bn * 4;
                if (h0) atomicAdd(&g_cnt[cb + 0], 1);
                if (h1) atomicAdd(&g_cnt[cb + 1], 1);
                if (h2) atomicAdd(&g_cnt[cb + 2], 1);
                if (h3) atomicAdd(&g_cnt[cb + 3], 1);
                if (atomicOr(&g_mark[bn], 1) == 0) {
                    int qq = atomicAdd(&g_qcnt, 1);
                    g_queue[qq] = bn;
                }
            }
        }
    }
    __syncthreads();
    for (int i = t; i < Nn; i += 512) {              // flush nonzero counters
        int c = hc[i];
        if (c) atomicAdd(&g_outdeg[gb + i], c);
    }
}

// ===========================================================================
// K_B: fixup (blocks [0,FBLK8)) + node fast path (blocks [FBLK8,+NODEB)).
// Block 0 also resets K_A's flags (runs strictly between K_A executions).
__global__ void __launch_bounds__(512, 2)
kb_kernel(const float* __restrict__ b1, const float* __restrict__ ln_g,
          const float* __restrict__ ln_b, const float* __restrict__ w2,
          const float* __restrict__ b2, float* __restrict__ out) {
    if (blockIdx.x == 0 && threadIdx.x == 0) {
        g_vecdone = 0u; g_cleandone = 0u;
        __threadfence();
    }
    if (blockIdx.x < FBLK8) {
        __shared__ float sdg[8];
        __shared__ float scc[8][4];
        __shared__ float* souts[8];
        int qn = g_qcnt;
        if (qn == 0) return;
        int t = threadIdx.x;
        for (int q0 = blockIdx.x * 8; q0 < qn; q0 += FBLK8 * 8) {
            if (t < 8) {
                int q = q0 + t; if (q >= qn) q = qn - 1;   // tail duplicate, benign
                int bn = g_queue[q];
                sdg[t] = (float)g_outdeg[bn];
                int4 c = *(const int4*)(g_cnt + (size_t)bn * 4);
                scc[t][0] = (float)c.x; scc[t][1] = (float)c.y;
                scc[t][2] = (float)c.z; scc[t][3] = (float)c.w;
                souts[t] = out + (size_t)bn * OUTD;
            }
            __syncthreads();
            pipeline8(sdg, scc, souts, b1, ln_g, ln_b, w2, b2);
            __syncthreads();
        }
        return;
    }
    int warp = (blockIdx.x - FBLK8) * 16 + (threadIdx.x >> 5);   // 4096 warps
    int lane = threadIdx.x & 31;
    int bn0  = warp * 8;

    int mk = 0, dgl = 0;
    if (lane < 8) { mk = g_mark[bn0 + lane]; dgl = g_outdeg[bn0 + lane]; }

    float2 v[8];
    int deg[8], mark[8];
    #pragma unroll
    for (int i = 0; i < 8; i++) {
        mark[i] = __shfl_sync(0xffffffffu, mk,  i);
        deg[i]  = __shfl_sync(0xffffffffu, dgl, i);
        int d = (deg[i] <= DCAP) ? deg[i] : DCAP;
        v[i] = __ldg((const float2*)(g_table + d * OUTD + lane * 2));  // MLP=8
    }
    // self-clean: unmarked nodes only dirtied outdeg (cnt/mark untouched)
    if (lane < 8 && !mk) g_outdeg[bn0 + lane] = 0;

    #pragma unroll
    for (int i = 0; i < 8; i++) {
        if (mark[i]) continue;                       // fixup path owns it
        if (deg[i] <= DCAP) {
            float2* dst = (float2*)(out + (size_t)(bn0 + i) * OUTD + lane * 2);
            __stcs(dst, v[i]);
            continue;
        }
        // --- never-taken safety path (Poisson(32)): in-warp full pipeline
        float dgf = (float)deg[i];
        float hreg[16];
        float ps = 0.f, pq = 0.f;
        #pragma unroll
        for (int r = 0; r < 16; r++) {
            int k = lane + 32 * r;
            float h = b1[k] + dgf * g_vec[k];
            hreg[r] = h; ps += h; pq += h * h;
        }
        #pragma unroll
        for (int o = 16; o > 0; o >>= 1) {
            ps += __shfl_xor_sync(0xffffffffu, ps, o);
            pq += __shfl_xor_sync(0xffffffffu, pq, o);
        }
        float mu  = ps * (1.f / HIDDEN);
        float var = pq * (1.f / HIDDEN) - mu * mu;
        float inv = rsqrtf(var + 1e-5f);
        #pragma unroll
        for (int r = 0; r < 16; r++) {
            int k = lane + 32 * r;
            float x = (hreg[r] - mu) * inv * ln_g[k] + ln_b[k];
            hreg[r] = 0.5f * x * (1.f + erff(x * 0.7071067811865476f));
        }
        for (int o = 0; o < OUTD; o++) {
            float acc = 0.f;
            const float* w2r = w2 + (size_t)o * HIDDEN + lane;
            #pragma unroll
            for (int r = 0; r < 16; r++) acc += hreg[r] * w2r[32 * r];
            #pragma unroll
            for (int off = 16; off > 0; off >>= 1)
                acc += __shfl_xor_sync(0xffffffffu, acc, off);
            if (lane == 0) out[(size_t)(bn0 + i) * OUTD + o] = acc + b2[o];
        }
    }
}

// ===========================================================================
extern "C" void kernel_launch(void* const* d_in, const int* in_sizes, int n_in,
                              void* d_out, int out_size) {
    const int*   ei     = (const int*)  d_in[0];
    const int*   pert   = (const int*)  d_in[1];
    const float* proj_w = (const float*)d_in[2];
    const float* proj_b = (const float*)d_in[3];
    const float* w1     = (const float*)d_in[4];
    const float* b1     = (const float*)d_in[5];
    const float* ln_g   = (const float*)d_in[6];
    const float* ln_b   = (const float*)d_in[7];
    const float* w2     = (const float*)d_in[8];
    const float* b2     = (const float*)d_in[9];
    float* out = (float*)d_out;

    ka_kernel<<<KA_NB, 512>>>(ei, pert, proj_w, proj_b, w1, b1, ln_g, ln_b, w2, b2);
    kb_kernel<<<FBLK8 + NODEB, 512>>>(b1, ln_g, ln_b, w2, b2, out);
}